// round 15
// baseline (speedup 1.0000x reference)
#include <cuda_runtime.h>
#include <cuda_bf16.h>
#include <cstdint>

// Problem constants
#define NN 8
#define AA 256
#define HH 128
#define WW 128
#define CC 19
#define CP1 20
#define HT 1024
#define WT 1024
#define RPB 8              // h-rows per stats block (8 -> grid 1024 fills 5 CTA/SM)
#define ACOLS 32           // a-columns per stats block
#define SEGW 22            // ushorts per ROW record: nseg + <=20 (cls<<8|start) + sentinel

// Device scratch (no cudaMalloc allowed)
__device__ float gSums[CP1 * AA];
__device__ float gSq[CP1 * AA];
__device__ float gCount[32];
__device__ float gS[CP1 * CC];
__device__ unsigned char gLab[NN * HH * WW];
__device__ unsigned char gPosT[NN * HH * WW];      // transposed: [row][w&31][w>>5] -> sorted pos
__device__ unsigned short gSegs[NN * HH * SEGW];   // per-row full-row segments
__device__ int gIs64;

// ---------------------------------------------------------------------------
// K0a: detect target dtype (int32 vs int64). int64 labels in [0,19): every
// odd 32-bit word is a zero high-word. Reads first 8192 words only (safe).
// ---------------------------------------------------------------------------
__global__ void detect_kernel(const int* __restrict__ tw) {
    __shared__ int anynz;
    if (threadIdx.x == 0) anynz = 0;
    __syncthreads();
    int v = 0;
    #pragma unroll
    for (int k = 0; k < 16; k++) {
        int idx = threadIdx.x * 16 + k;          // 0..4095
        v |= tw[idx * 2 + 1];                    // word idx <= 8191
    }
    if (v != 0) atomicOr(&anynz, 1);
    __syncthreads();
    if (threadIdx.x == 0) gIs64 = (anynz == 0) ? 1 : 0;
}

// ---------------------------------------------------------------------------
// K0b: zero the per-class accumulators
// ---------------------------------------------------------------------------
__global__ void zero_kernel() {
    int i = blockIdx.x * 256 + threadIdx.x;
    if (i < CP1 * AA) { gSums[i] = 0.f; gSq[i] = 0.f; }
    if (i < 32) gCount[i] = 0.f;
}

// ---------------------------------------------------------------------------
// K0c: per-row label fetch + counting sort + full-row segment extraction.
// One block per (n,h) row. Writes gPosT (sorted position of each pixel,
// transposed so stats threads load uchar4), gSegs (nseg, then (cls<<8|start)
// runs over the sorted row + sentinel 128), gLab (raw bytes), gCount.
// ---------------------------------------------------------------------------
__global__ void sort_kernel(const int* __restrict__ tw) {
    __shared__ int cnt[CP1];
    __shared__ int offs[CP1];
    __shared__ unsigned char slab[128];
    const int t = threadIdx.x;          // 0..127 (w)
    const int row = blockIdx.x;         // n*HH + h
    const int n = row >> 7;
    const int h = row & 127;

    long long eidx = ((long long)n * HT + (long long)h * 8) * WT + (long long)t * 8;
    int raw = gIs64 ? tw[eidx * 2] : tw[eidx];
    int l0 = (raw == 255) ? 0 : raw;
    if (l0 < 0) l0 = 0;
    if (l0 > CP1 - 1) l0 = CP1 - 1;

    if (t < CP1) cnt[t] = 0;
    __syncthreads();
    atomicAdd(&cnt[l0], 1);
    gLab[(size_t)row * WW + t] = (unsigned char)(raw & 0xFF);
    __syncthreads();
    if (t == 0) {
        int run = 0;
        #pragma unroll
        for (int c = 0; c < CP1; c++) { offs[c] = run; run += cnt[c]; }
    }
    if (t < CP1) atomicAdd(&gCount[t], (float)cnt[t]);
    __syncthreads();
    int pos = atomicAdd(&offs[l0], 1);
    slab[pos] = (unsigned char)l0;
    gPosT[((size_t)row * 32 + (t & 31)) * 4 + (t >> 5)] = (unsigned char)pos;
    __syncthreads();

    // full-row segment extraction (thread 0, serial scan of 128)
    if (t == 0) {
        unsigned short* out = gSegs + (size_t)row * SEGW;
        int run = slab[0];
        out[1] = (unsigned short)(run << 8);     // start = 0
        int ns = 1;
        #pragma unroll 1
        for (int i = 1; i < 128; i++) {
            int c = slab[i];
            if (c != run) {
                out[1 + ns] = (unsigned short)((c << 8) | i);
                ns++; run = c;
            }
        }
        out[1 + ns] = 128;                       // sentinel: start = 128
        out[0] = (unsigned short)ns;
    }
}

// ---------------------------------------------------------------------------
// K1: stats. Block = (a-eighth of 32, h-block of 8 rows, n) -> 1024 blocks.
// 256 threads, 38.6KB dynamic smem, reg-capped at 5 CTA/SM; grid 1024 now
// FILLS the 740 resident slots (R14's grid 512 left occupancy at 3.46 CTA).
// Permuted staging: features scattered to sorted positions at STS time
// (uchar4 position load per thread per row, prefetched) -> accum reads are
// sequential LDS + 2 FFMA per pixel. Full-row segments split across 8 warps
// by index mod 8 (class-disjoint -> race-free bins [20][32]). One coalesced
// atomic flush per block.
// ---------------------------------------------------------------------------
__global__ __launch_bounds__(256, 5)
void stats_kernel(const float* __restrict__ features) {
    extern __shared__ float sm[];
    float* buf  = sm;                              // [2][ACOLS*129]  33024 B
    float* accS = sm + 2 * ACOLS * 129;            // [CP1][32]  2560 B
    float* accQ = accS + CP1 * 32;                 // [CP1][32]  2560 B
    unsigned short* segsm = (unsigned short*)(accQ + CP1 * 32);   // [RPB*SEGW] 352 B

    const int t    = threadIdx.x;       // 0..255
    const int lane = t & 31;            // a-column (accum) / w-lane (staging)
    const int wr   = t >> 5;            // warp 0..7
    const int q    = blockIdx.x;        // a-eighth 0..7
    const int hb   = blockIdx.y;        // 0..15
    const int n    = blockIdx.z;
    const int aBase = q * ACOLS;
    const int row0  = n * HH + hb * RPB;

    // zero accumulators + preload segment metadata for the 8 rows
    #pragma unroll
    for (int i = t; i < 2 * CP1 * 32; i += 256) accS[i] = 0.f;   // covers accS+accQ
    #pragma unroll
    for (int i = t; i < RPB * SEGW; i += 256) segsm[i] = gSegs[(size_t)row0 * SEGW + i];

    const float* fbase = features + ((size_t)(n * AA + aBase)) * (HH * WW)
                       + (size_t)(hb * RPB) * WW;
    const unsigned char* ptbase = gPosT + ((size_t)row0 * 32 + lane) * 4;

    // prologue: positions + features of row 0 (warp wr stages a-rows wr+8k)
    uchar4 pv = *(const uchar4*)ptbase;
    float pf[16];
    #pragma unroll
    for (int k = 0; k < 4; k++)
        #pragma unroll
        for (int m = 0; m < 4; m++)
            pf[k * 4 + m] = fbase[(size_t)(wr + 8 * k) * (HH * WW) + lane + 32 * m];

    __syncthreads();   // metadata + acc zero visible

    #pragma unroll 1
    for (int ch = 0; ch < RPB; ch++) {
        float* bufc = buf + (ch & 1) * (ACOLS * 129);

        // scatter current row tile into sorted order (stride 129)
        #pragma unroll
        for (int k = 0; k < 4; k++) {
            int rb = (wr + 8 * k) * 129;
            bufc[rb + pv.x] = pf[k * 4 + 0];
            bufc[rb + pv.y] = pf[k * 4 + 1];
            bufc[rb + pv.z] = pf[k * 4 + 2];
            bufc[rb + pv.w] = pf[k * 4 + 3];
        }

        // prefetch next row's positions + features (consumed at ch+1's STS)
        uchar4 pvn = pv;
        if (ch + 1 < RPB) {
            pvn = *(const uchar4*)(ptbase + (ch + 1) * (32 * 4));
            #pragma unroll
            for (int k = 0; k < 4; k++)
                #pragma unroll
                for (int m = 0; m < 4; m++)
                    pf[k * 4 + m] = fbase[(size_t)(wr + 8 * k) * (HH * WW)
                                          + (ch + 1) * WW + lane + 32 * m];
        }
        __syncthreads();   // stage filled; orders accum(ch-1) vs STS(ch+1)

        // full-row segment accumulation: warp wr takes segments si == wr (mod 8)
        // bufc is in sorted order -> sequential reads, LDS + 2 FFMA per pixel
        {
            const unsigned short* sgr = segsm + ch * SEGW;
            const int nseg = sgr[0];
            const float* bp = bufc + lane * 129;
            #pragma unroll 1
            for (int si = 1 + wr; si <= nseg; si += 8) {
                int e     = sgr[si];               // uniform LDS
                int cls   = e >> 8;
                int start = e & 255;
                int end   = sgr[si + 1] & 255;     // next start / sentinel 128
                float s = 0.f, qq = 0.f;
                #pragma unroll 2
                for (int j = start; j < end; j++) {
                    float f = bp[j];               // sequential, conflict-free
                    s  += f;
                    qq += f * f;
                }
                accS[cls * 32 + lane] += s;        // race-free: class-disjoint mod 8
                accQ[cls * 32 + lane] += qq;
            }
        }
        pv = pvn;
    }
    __syncthreads();

    // single coalesced atomic flush
    #pragma unroll
    for (int i = t; i < CP1 * 32; i += 256) {
        int c = i >> 5, al = i & 31;
        atomicAdd(&gSums[c * AA + aBase + al], accS[i]);
        atomicAdd(&gSq[c * AA + aBase + al],   accQ[i]);
    }
}

// ---------------------------------------------------------------------------
// K2: grid = 361 blocks, one per (l,c) pair (ncov row 19 never read:
// lab0<=18). Each block recomputes ncov[l,:] pointwise (cheap) and reduces
// ratio * sum_a ncov[l,a]*(W[c,a]-W[l,a])^2 across 256 threads.
// ---------------------------------------------------------------------------
__global__ __launch_bounds__(256)
void cov_s_kernel(const float* __restrict__ fc,
                  const float* __restrict__ Ave,
                  const float* __restrict__ CoV,
                  const float* __restrict__ Amount,
                  const int* __restrict__ ratio_p) {
    __shared__ float red[8];
    const int l = blockIdx.x / CC;     // 0..18
    const int c = blockIdx.x % CC;     // 0..18
    const int t = threadIdx.x;         // 0..255 == feature index a
    const int lane = t & 31, wid = t >> 5;

    float cntv = gCount[l];
    float sums = gSums[l * AA + t];
    float sq   = gSq[l * AA + t];
    float avev = Ave[l * AA + t];
    float covv = CoV[l * AA + t];
    float amov = Amount[l];
    float wc   = fc[c * AA + t];
    float wl   = fc[l * AA + t];
    float r    = (float)(*ratio_p);    // low 4 LE bytes: correct for i32 & i64

    float cntc = (cntv == 0.f) ? 1.f : cntv;
    float ave  = sums / cntc;
    float var  = sq / cntc - ave * ave;
    float denom = cntv + amov;
    float wcv  = (denom > 0.f) ? (cntv / denom) : 0.f;
    float dd   = avev - ave;
    float ncov = covv * (1.f - wcv) + var * wcv + wcv * (1.f - wcv) * dd * dd;

    float d = wc - wl;
    float v = ncov * d * d;
    #pragma unroll
    for (int o = 16; o; o >>= 1) v += __shfl_down_sync(0xffffffffu, v, o);
    if (lane == 0) red[wid] = v;
    __syncthreads();
    if (t == 0) {
        float s = 0.f;
        #pragma unroll
        for (int k = 0; k < 8; k++) s += red[k];
        gS[l * CC + c] = r * s;
    }
}

// ---------------------------------------------------------------------------
// K3: out[n,c,h,w] = y[n,c,h,w] + 0.5 * S[l(n,h,w), c] * (l != 255)
// 4 blocks per (n,c) -> 608 blocks, 256 threads, float4/uchar4
// ---------------------------------------------------------------------------
__global__ __launch_bounds__(256, 4)
void aug_kernel(const float* __restrict__ y, float* __restrict__ out) {
    __shared__ float Ssm[CP1];
    const int t = threadIdx.x;                 // 0..255
    const int bq = blockIdx.x & 3;             // h-quarter
    const int nc = blockIdx.x >> 2;
    const int n = nc / CC;
    const int c = nc % CC;

    if (t < CP1) Ssm[t] = (t < CC) ? (0.5f * gS[t * CC + c]) : 0.f;
    __syncthreads();

    const size_t plane = ((size_t)n * CC + c) * (HH * WW);
    const int qoff = bq * (HH * WW / 16);      // in float4 units
    const float4* y4 = (const float4*)(y + plane) + qoff;
    float4*       o4 = (float4*)(out + plane) + qoff;
    const uchar4* l4 = (const uchar4*)(gLab + (size_t)n * (HH * WW)) + qoff;

    #pragma unroll 4
    for (int i = t; i < (HH * WW) / 16; i += 256) {
        uchar4 lb = l4[i];
        float4 v  = y4[i];
        if (lb.x != 255) v.x += Ssm[lb.x];
        if (lb.y != 255) v.y += Ssm[lb.y];
        if (lb.z != 255) v.z += Ssm[lb.z];
        if (lb.w != 255) v.w += Ssm[lb.w];
        o4[i] = v;
    }
}

// ---------------------------------------------------------------------------
extern "C" void kernel_launch(void* const* d_in, const int* in_sizes, int n_in,
                              void* d_out, int out_size) {
    const float* features = (const float*)d_in[0];
    const float* y        = (const float*)d_in[1];
    const float* fc       = (const float*)d_in[2];
    const float* Ave      = (const float*)d_in[3];
    const float* CoV      = (const float*)d_in[4];
    const float* Amount   = (const float*)d_in[5];
    const int*   target_w = (const int*)d_in[6];   // int32 or int64 (probed)
    const int*   ratio    = (const int*)d_in[7];
    float*       out      = (float*)d_out;

    // launch idx 0: dtype probe
    detect_kernel<<<1, 256>>>(target_w);
    // launch idx 1: zero accumulators
    zero_kernel<<<(CP1 * AA + 255) / 256, 256>>>();
    // launch idx 2: per-row label sort + position/segment extraction
    sort_kernel<<<NN * HH, 128>>>(target_w);

    // launch idx 3 (the ncu-captured slot): stats
    const int smem1 = (2 * ACOLS * 129 + 2 * CP1 * 32) * 4 + RPB * SEGW * 2;
    cudaFuncSetAttribute(stats_kernel, cudaFuncAttributeMaxDynamicSharedMemorySize, smem1);
    dim3 g1(8, HH / RPB, NN);
    stats_kernel<<<g1, 256, smem1>>>(features);

    // launch idx 4: covariance update + S table (one block per (l,c))
    cov_s_kernel<<<CC * CC, 256>>>(fc, Ave, CoV, Amount, ratio);

    // launch idx 5: output
    aug_kernel<<<NN * CC * 4, 256>>>(y, out);
}

// round 16
// speedup vs baseline: 1.0291x; 1.0291x over previous
#include <cuda_runtime.h>
#include <cuda_bf16.h>
#include <cstdint>

// Problem constants
#define NN 8
#define AA 256
#define HH 128
#define WW 128
#define CC 19
#define CP1 20
#define HT 1024
#define WT 1024
#define RPB 16             // h-rows per stats block (R14 config: best measured)
#define ACOLS 32           // a-columns per stats block
#define SEGW 22            // ushorts per ROW record: nseg + <=20 (cls<<8|start) + sentinel

// Device scratch (no cudaMalloc allowed)
__device__ float gSums[CP1 * AA];
__device__ float gSq[CP1 * AA];
__device__ float gCount[32];
__device__ float gS[CP1 * CC];
__device__ unsigned char gLab[NN * HH * WW];
__device__ unsigned char gPosT[NN * HH * WW];      // transposed: [row][w&31][w>>5] -> sorted pos
__device__ unsigned short gSegs[NN * HH * SEGW];   // per-row full-row segments

// ---------------------------------------------------------------------------
// K0: FUSED sort + zero + local dtype detect. One block per (n,h) row.
//  - local detect: every block samples the same 2048 safe odd 32-bit words
//    (indices < 4096 elements -> in-bounds for both dtypes); for int64 labels
//    in [0,19) they are all zero high-words; for int32 random labels the
//    probability of all-zero is (1/19)^2048 ~ 0. All blocks agree.
//  - zero: each block zeroes a disjoint 5-float slice of gSums & gSq
//    (1024 blocks x 5 = 5120 = CP1*AA); block 0 zeroes gCount.
//  - sort: counting sort of the row's 128 downsampled labels; writes gPosT
//    (sorted position per pixel, transposed for uchar4 loads), gSegs
//    (full-row class segments + sentinel), gLab (raw bytes).
// ---------------------------------------------------------------------------
__global__ void sort_kernel(const int* __restrict__ tw) {
    __shared__ int anynz;
    __shared__ int cnt[CP1];
    __shared__ int offs[CP1];
    __shared__ unsigned char slab[128];
    const int t = threadIdx.x;          // 0..127 (w)
    const int row = blockIdx.x;         // n*HH + h
    const int n = row >> 7;
    const int h = row & 127;

    if (t == 0) anynz = 0;
    // zero accumulator slices (5 floats per array per block)
    if (t < 5) {
        int i = row * 5 + t;            // < 5120 = CP1*AA
        gSums[i] = 0.f;
        gSq[i]   = 0.f;
    }
    if (row == 0 && t < 32) gCount[t] = 0.f;
    __syncthreads();

    // local dtype probe (same safe region for every block; L2-cached)
    {
        int v = 0;
        #pragma unroll
        for (int k = 0; k < 16; k++) {
            int idx = t * 16 + k;            // 0..2047 elements
            v |= tw[idx * 2 + 1];            // word idx <= 4095: safe both dtypes
        }
        if (v != 0) atomicOr(&anynz, 1);
    }
    __syncthreads();
    const int is64 = (anynz == 0) ? 1 : 0;

    long long eidx = ((long long)n * HT + (long long)h * 8) * WT + (long long)t * 8;
    int raw = is64 ? tw[eidx * 2] : tw[eidx];
    int l0 = (raw == 255) ? 0 : raw;
    if (l0 < 0) l0 = 0;
    if (l0 > CP1 - 1) l0 = CP1 - 1;

    if (t < CP1) cnt[t] = 0;
    __syncthreads();
    atomicAdd(&cnt[l0], 1);
    gLab[(size_t)row * WW + t] = (unsigned char)(raw & 0xFF);
    __syncthreads();
    if (t == 0) {
        int run = 0;
        #pragma unroll
        for (int c = 0; c < CP1; c++) { offs[c] = run; run += cnt[c]; }
    }
    __syncthreads();
    int pos = atomicAdd(&offs[l0], 1);
    slab[pos] = (unsigned char)l0;
    gPosT[((size_t)row * 32 + (t & 31)) * 4 + (t >> 5)] = (unsigned char)pos;
    __syncthreads();

    // full-row segment extraction (thread 0, serial scan of 128)
    if (t == 0) {
        unsigned short* out = gSegs + (size_t)row * SEGW;
        int run = slab[0];
        out[1] = (unsigned short)(run << 8);     // start = 0
        int ns = 1;
        #pragma unroll 1
        for (int i = 1; i < 128; i++) {
            int c = slab[i];
            if (c != run) {
                out[1 + ns] = (unsigned short)((c << 8) | i);
                ns++; run = c;
            }
        }
        out[1 + ns] = 128;                       // sentinel: start = 128
        out[0] = (unsigned short)ns;
    }
}

// ---------------------------------------------------------------------------
// K1: stats (R14 config — best measured). Block = (a-eighth of 32, 16 rows,
// n) -> 512 blocks, 256 threads, 38.9KB smem.
// Permuted staging: features scattered to their sorted positions at STS time
// (uchar4 position load per thread per row, prefetched with pf) -> the accum
// loop reads SEQUENTIAL addresses: LDS + 2 FFMA per pixel, zero index math.
// Full-row segments split across 8 warps by index mod 8 (class-disjoint ->
// race-free single-copy bins [20][32]). One coalesced atomic flush per block.
// NEW: q==0 blocks also accumulate gCount from segment lengths (replaces the
// old sort-kernel atomics; gCount zeroed by sort block 0).
// ---------------------------------------------------------------------------
__global__ __launch_bounds__(256, 5)
void stats_kernel(const float* __restrict__ features) {
    extern __shared__ float sm[];
    float* buf  = sm;                              // [2][ACOLS*129]  33024 B
    float* accS = sm + 2 * ACOLS * 129;            // [CP1][32]  2560 B
    float* accQ = accS + CP1 * 32;                 // [CP1][32]  2560 B
    float* ccnt = accQ + CP1 * 32;                 // [CP1]      80 B
    unsigned short* segsm = (unsigned short*)(ccnt + CP1);   // [RPB*SEGW] 704 B

    const int t    = threadIdx.x;       // 0..255
    const int lane = t & 31;            // a-column (accum) / w-lane (staging)
    const int wr   = t >> 5;            // warp 0..7
    const int q    = blockIdx.x;        // a-eighth 0..7
    const int hb   = blockIdx.y;        // 0..7
    const int n    = blockIdx.z;
    const int aBase = q * ACOLS;
    const int row0  = n * HH + hb * RPB;

    // zero accumulators + preload segment metadata for the 16 rows
    #pragma unroll
    for (int i = t; i < 2 * CP1 * 32; i += 256) accS[i] = 0.f;   // covers accS+accQ
    if (t < CP1) ccnt[t] = 0.f;
    #pragma unroll
    for (int i = t; i < RPB * SEGW; i += 256) segsm[i] = gSegs[(size_t)row0 * SEGW + i];

    const float* fbase = features + ((size_t)(n * AA + aBase)) * (HH * WW)
                       + (size_t)(hb * RPB) * WW;
    const unsigned char* ptbase = gPosT + ((size_t)row0 * 32 + lane) * 4;

    // prologue: positions + features of row 0 (warp wr stages a-rows wr+8k)
    uchar4 pv = *(const uchar4*)ptbase;
    float pf[16];
    #pragma unroll
    for (int k = 0; k < 4; k++)
        #pragma unroll
        for (int m = 0; m < 4; m++)
            pf[k * 4 + m] = fbase[(size_t)(wr + 8 * k) * (HH * WW) + lane + 32 * m];

    __syncthreads();   // metadata + acc zero visible

    // gCount from segment lengths (q==0 blocks only; block-uniform branch)
    if (q == 0) {
        if (t < RPB) {
            const unsigned short* sgr = segsm + t * SEGW;
            int ns = sgr[0];
            #pragma unroll 1
            for (int si = 1; si <= ns; si++) {
                int cls = sgr[si] >> 8;
                int len = (sgr[si + 1] & 255) - (sgr[si] & 255);
                atomicAdd(&ccnt[cls], (float)len);
            }
        }
        __syncthreads();
        if (t < CP1 && ccnt[t] != 0.f) atomicAdd(&gCount[t], ccnt[t]);
    }

    #pragma unroll 1
    for (int ch = 0; ch < RPB; ch++) {
        float* bufc = buf + (ch & 1) * (ACOLS * 129);

        // scatter current row tile into sorted order (stride 129)
        #pragma unroll
        for (int k = 0; k < 4; k++) {
            int rb = (wr + 8 * k) * 129;
            bufc[rb + pv.x] = pf[k * 4 + 0];
            bufc[rb + pv.y] = pf[k * 4 + 1];
            bufc[rb + pv.z] = pf[k * 4 + 2];
            bufc[rb + pv.w] = pf[k * 4 + 3];
        }

        // prefetch next row's positions + features (consumed at ch+1's STS)
        uchar4 pvn = pv;
        if (ch + 1 < RPB) {
            pvn = *(const uchar4*)(ptbase + (ch + 1) * (32 * 4));
            #pragma unroll
            for (int k = 0; k < 4; k++)
                #pragma unroll
                for (int m = 0; m < 4; m++)
                    pf[k * 4 + m] = fbase[(size_t)(wr + 8 * k) * (HH * WW)
                                          + (ch + 1) * WW + lane + 32 * m];
        }
        __syncthreads();   // stage filled; orders accum(ch-1) vs STS(ch+1)

        // full-row segment accumulation: warp wr takes segments si == wr (mod 8)
        // bufc is in sorted order -> sequential reads, LDS + 2 FFMA per pixel
        {
            const unsigned short* sgr = segsm + ch * SEGW;
            const int nseg = sgr[0];
            const float* bp = bufc + lane * 129;
            #pragma unroll 1
            for (int si = 1 + wr; si <= nseg; si += 8) {
                int e     = sgr[si];               // uniform LDS
                int cls   = e >> 8;
                int start = e & 255;
                int end   = sgr[si + 1] & 255;     // next start / sentinel 128
                float s = 0.f, qq = 0.f;
                #pragma unroll 2
                for (int j = start; j < end; j++) {
                    float f = bp[j];               // sequential, conflict-free
                    s  += f;
                    qq += f * f;
                }
                accS[cls * 32 + lane] += s;        // race-free: class-disjoint mod 8
                accQ[cls * 32 + lane] += qq;
            }
        }
        pv = pvn;
    }
    __syncthreads();

    // single coalesced atomic flush
    #pragma unroll
    for (int i = t; i < CP1 * 32; i += 256) {
        int c = i >> 5, al = i & 31;
        atomicAdd(&gSums[c * AA + aBase + al], accS[i]);
        atomicAdd(&gSq[c * AA + aBase + al],   accQ[i]);
    }
}

// ---------------------------------------------------------------------------
// K2: grid = 361 blocks, one per (l,c) pair (ncov row 19 never read:
// lab0<=18). Each block recomputes ncov[l,:] pointwise (cheap) and reduces
// ratio * sum_a ncov[l,a]*(W[c,a]-W[l,a])^2 across 256 threads.
// ---------------------------------------------------------------------------
__global__ __launch_bounds__(256)
void cov_s_kernel(const float* __restrict__ fc,
                  const float* __restrict__ Ave,
                  const float* __restrict__ CoV,
                  const float* __restrict__ Amount,
                  const int* __restrict__ ratio_p) {
    __shared__ float red[8];
    const int l = blockIdx.x / CC;     // 0..18
    const int c = blockIdx.x % CC;     // 0..18
    const int t = threadIdx.x;         // 0..255 == feature index a
    const int lane = t & 31, wid = t >> 5;

    float cntv = gCount[l];
    float sums = gSums[l * AA + t];
    float sq   = gSq[l * AA + t];
    float avev = Ave[l * AA + t];
    float covv = CoV[l * AA + t];
    float amov = Amount[l];
    float wc   = fc[c * AA + t];
    float wl   = fc[l * AA + t];
    float r    = (float)(*ratio_p);    // low 4 LE bytes: correct for i32 & i64

    float cntc = (cntv == 0.f) ? 1.f : cntv;
    float ave  = sums / cntc;
    float var  = sq / cntc - ave * ave;
    float denom = cntv + amov;
    float wcv  = (denom > 0.f) ? (cntv / denom) : 0.f;
    float dd   = avev - ave;
    float ncov = covv * (1.f - wcv) + var * wcv + wcv * (1.f - wcv) * dd * dd;

    float d = wc - wl;
    float v = ncov * d * d;
    #pragma unroll
    for (int o = 16; o; o >>= 1) v += __shfl_down_sync(0xffffffffu, v, o);
    if (lane == 0) red[wid] = v;
    __syncthreads();
    if (t == 0) {
        float s = 0.f;
        #pragma unroll
        for (int k = 0; k < 8; k++) s += red[k];
        gS[l * CC + c] = r * s;
    }
}

// ---------------------------------------------------------------------------
// K3: out[n,c,h,w] = y[n,c,h,w] + 0.5 * S[l(n,h,w), c] * (l != 255)
// 4 blocks per (n,c) -> 608 blocks, 256 threads, float4/uchar4
// ---------------------------------------------------------------------------
__global__ __launch_bounds__(256, 4)
void aug_kernel(const float* __restrict__ y, float* __restrict__ out) {
    __shared__ float Ssm[CP1];
    const int t = threadIdx.x;                 // 0..255
    const int bq = blockIdx.x & 3;             // h-quarter
    const int nc = blockIdx.x >> 2;
    const int n = nc / CC;
    const int c = nc % CC;

    if (t < CP1) Ssm[t] = (t < CC) ? (0.5f * gS[t * CC + c]) : 0.f;
    __syncthreads();

    const size_t plane = ((size_t)n * CC + c) * (HH * WW);
    const int qoff = bq * (HH * WW / 16);      // in float4 units
    const float4* y4 = (const float4*)(y + plane) + qoff;
    float4*       o4 = (float4*)(out + plane) + qoff;
    const uchar4* l4 = (const uchar4*)(gLab + (size_t)n * (HH * WW)) + qoff;

    #pragma unroll 4
    for (int i = t; i < (HH * WW) / 16; i += 256) {
        uchar4 lb = l4[i];
        float4 v  = y4[i];
        if (lb.x != 255) v.x += Ssm[lb.x];
        if (lb.y != 255) v.y += Ssm[lb.y];
        if (lb.z != 255) v.z += Ssm[lb.z];
        if (lb.w != 255) v.w += Ssm[lb.w];
        o4[i] = v;
    }
}

// ---------------------------------------------------------------------------
extern "C" void kernel_launch(void* const* d_in, const int* in_sizes, int n_in,
                              void* d_out, int out_size) {
    const float* features = (const float*)d_in[0];
    const float* y        = (const float*)d_in[1];
    const float* fc       = (const float*)d_in[2];
    const float* Ave      = (const float*)d_in[3];
    const float* CoV      = (const float*)d_in[4];
    const float* Amount   = (const float*)d_in[5];
    const int*   target_w = (const int*)d_in[6];   // int32 or int64 (probed per-block)
    const int*   ratio    = (const int*)d_in[7];
    float*       out      = (float*)d_out;

    // launch 0: fused sort + zero + dtype detect
    sort_kernel<<<NN * HH, 128>>>(target_w);

    // launch 1: stats (+ gCount from segments)
    const int smem1 = (2 * ACOLS * 129 + 2 * CP1 * 32 + CP1) * 4 + RPB * SEGW * 2;
    cudaFuncSetAttribute(stats_kernel, cudaFuncAttributeMaxDynamicSharedMemorySize, smem1);
    dim3 g1(8, HH / RPB, NN);
    stats_kernel<<<g1, 256, smem1>>>(features);

    // launch 2: covariance update + S table (one block per (l,c))
    cov_s_kernel<<<CC * CC, 256>>>(fc, Ave, CoV, Amount, ratio);

    // launch 3: output
    aug_kernel<<<NN * CC * 4, 256>>>(y, out);
}

// round 17
// speedup vs baseline: 1.2524x; 1.2169x over previous
#include <cuda_runtime.h>
#include <cuda_bf16.h>
#include <cstdint>

// Problem constants
#define NN 8
#define AA 256
#define HH 128
#define WW 128
#define CC 19
#define CP1 20
#define HT 1024
#define WT 1024
#define RPB 16             // h-rows per stats block (R14 config: best measured)
#define ACOLS 32           // a-columns per stats block
#define SEGW 22            // ushorts per ROW record: nseg + <=20 (cls<<8|start) + sentinel

// Device scratch (no cudaMalloc allowed)
__device__ float gSums[CP1 * AA];
__device__ float gSq[CP1 * AA];
__device__ float gCount[32];
__device__ float gS[CP1 * CC];
__device__ unsigned char gLab[NN * HH * WW];
__device__ unsigned char gPosT[NN * HH * WW];      // transposed: [row][w&31][w>>5] -> sorted pos
__device__ unsigned short gSegs[NN * HH * SEGW];   // per-row full-row segments
__device__ int gIs64;

// ---------------------------------------------------------------------------
// K0a: detect target dtype (int32 vs int64). int64 labels in [0,19): every
// odd 32-bit word is a zero high-word. Reads first 8192 words only (safe).
// ---------------------------------------------------------------------------
__global__ void detect_kernel(const int* __restrict__ tw) {
    __shared__ int anynz;
    if (threadIdx.x == 0) anynz = 0;
    __syncthreads();
    int v = 0;
    #pragma unroll
    for (int k = 0; k < 16; k++) {
        int idx = threadIdx.x * 16 + k;          // 0..4095
        v |= tw[idx * 2 + 1];                    // word idx <= 8191
    }
    if (v != 0) atomicOr(&anynz, 1);
    __syncthreads();
    if (threadIdx.x == 0) gIs64 = (anynz == 0) ? 1 : 0;
}

// ---------------------------------------------------------------------------
// K0b: zero the per-class accumulators
// ---------------------------------------------------------------------------
__global__ void zero_kernel() {
    int i = blockIdx.x * 256 + threadIdx.x;
    if (i < CP1 * AA) { gSums[i] = 0.f; gSq[i] = 0.f; }
    if (i < 32) gCount[i] = 0.f;
}

// ---------------------------------------------------------------------------
// K0c: per-row label fetch + counting sort + full-row segment extraction.
// One block per (n,h) row. Writes gPosT (sorted position of each pixel,
// transposed so stats threads load uchar4), gSegs (nseg, then (cls<<8|start)
// runs over the sorted row + sentinel 128), gLab (raw bytes), gCount.
// ---------------------------------------------------------------------------
__global__ void sort_kernel(const int* __restrict__ tw) {
    __shared__ int cnt[CP1];
    __shared__ int offs[CP1];
    __shared__ unsigned char slab[128];
    const int t = threadIdx.x;          // 0..127 (w)
    const int row = blockIdx.x;         // n*HH + h
    const int n = row >> 7;
    const int h = row & 127;

    long long eidx = ((long long)n * HT + (long long)h * 8) * WT + (long long)t * 8;
    int raw = gIs64 ? tw[eidx * 2] : tw[eidx];
    int l0 = (raw == 255) ? 0 : raw;
    if (l0 < 0) l0 = 0;
    if (l0 > CP1 - 1) l0 = CP1 - 1;

    if (t < CP1) cnt[t] = 0;
    __syncthreads();
    atomicAdd(&cnt[l0], 1);
    gLab[(size_t)row * WW + t] = (unsigned char)(raw & 0xFF);
    __syncthreads();
    if (t == 0) {
        int run = 0;
        #pragma unroll
        for (int c = 0; c < CP1; c++) { offs[c] = run; run += cnt[c]; }
    }
    if (t < CP1) atomicAdd(&gCount[t], (float)cnt[t]);
    __syncthreads();
    int pos = atomicAdd(&offs[l0], 1);
    slab[pos] = (unsigned char)l0;
    gPosT[((size_t)row * 32 + (t & 31)) * 4 + (t >> 5)] = (unsigned char)pos;
    __syncthreads();

    // full-row segment extraction (thread 0, serial scan of 128)
    if (t == 0) {
        unsigned short* out = gSegs + (size_t)row * SEGW;
        int run = slab[0];
        out[1] = (unsigned short)(run << 8);     // start = 0
        int ns = 1;
        #pragma unroll 1
        for (int i = 1; i < 128; i++) {
            int c = slab[i];
            if (c != run) {
                out[1 + ns] = (unsigned short)((c << 8) | i);
                ns++; run = c;
            }
        }
        out[1 + ns] = 128;                       // sentinel: start = 128
        out[0] = (unsigned short)ns;
    }
}

// ---------------------------------------------------------------------------
// K1: stats (R14 config — best measured: 36.4us). Block = (a-eighth of 32,
// 16 rows, n) -> 512 blocks, 256 threads, 38.9KB smem.
// Permuted staging: features scattered to their sorted positions at STS time
// (uchar4 position load per thread per row, prefetched with pf) -> the accum
// loop reads SEQUENTIAL addresses: LDS + 2 FFMA per pixel, zero index math.
// Full-row segments split across 8 warps by index mod 8 (class-disjoint ->
// race-free single-copy bins [20][32]). One coalesced atomic flush per block.
// ---------------------------------------------------------------------------
__global__ __launch_bounds__(256, 5)
void stats_kernel(const float* __restrict__ features) {
    extern __shared__ float sm[];
    float* buf  = sm;                              // [2][ACOLS*129]  33024 B
    float* accS = sm + 2 * ACOLS * 129;            // [CP1][32]  2560 B
    float* accQ = accS + CP1 * 32;                 // [CP1][32]  2560 B
    unsigned short* segsm = (unsigned short*)(accQ + CP1 * 32);   // [RPB*SEGW] 704 B

    const int t    = threadIdx.x;       // 0..255
    const int lane = t & 31;            // a-column (accum) / w-lane (staging)
    const int wr   = t >> 5;            // warp 0..7
    const int q    = blockIdx.x;        // a-eighth 0..7
    const int hb   = blockIdx.y;        // 0..7
    const int n    = blockIdx.z;
    const int aBase = q * ACOLS;
    const int row0  = n * HH + hb * RPB;

    // zero accumulators + preload segment metadata for the 16 rows
    #pragma unroll
    for (int i = t; i < 2 * CP1 * 32; i += 256) accS[i] = 0.f;   // covers accS+accQ
    #pragma unroll
    for (int i = t; i < RPB * SEGW; i += 256) segsm[i] = gSegs[(size_t)row0 * SEGW + i];

    const float* fbase = features + ((size_t)(n * AA + aBase)) * (HH * WW)
                       + (size_t)(hb * RPB) * WW;
    const unsigned char* ptbase = gPosT + ((size_t)row0 * 32 + lane) * 4;

    // prologue: positions + features of row 0 (warp wr stages a-rows wr+8k)
    uchar4 pv = *(const uchar4*)ptbase;
    float pf[16];
    #pragma unroll
    for (int k = 0; k < 4; k++)
        #pragma unroll
        for (int m = 0; m < 4; m++)
            pf[k * 4 + m] = fbase[(size_t)(wr + 8 * k) * (HH * WW) + lane + 32 * m];

    __syncthreads();   // metadata + acc zero visible

    #pragma unroll 1
    for (int ch = 0; ch < RPB; ch++) {
        float* bufc = buf + (ch & 1) * (ACOLS * 129);

        // scatter current row tile into sorted order (stride 129)
        #pragma unroll
        for (int k = 0; k < 4; k++) {
            int rb = (wr + 8 * k) * 129;
            bufc[rb + pv.x] = pf[k * 4 + 0];
            bufc[rb + pv.y] = pf[k * 4 + 1];
            bufc[rb + pv.z] = pf[k * 4 + 2];
            bufc[rb + pv.w] = pf[k * 4 + 3];
        }

        // prefetch next row's positions + features (consumed at ch+1's STS)
        uchar4 pvn = pv;
        if (ch + 1 < RPB) {
            pvn = *(const uchar4*)(ptbase + (ch + 1) * (32 * 4));
            #pragma unroll
            for (int k = 0; k < 4; k++)
                #pragma unroll
                for (int m = 0; m < 4; m++)
                    pf[k * 4 + m] = fbase[(size_t)(wr + 8 * k) * (HH * WW)
                                          + (ch + 1) * WW + lane + 32 * m];
        }
        __syncthreads();   // stage filled; orders accum(ch-1) vs STS(ch+1)

        // full-row segment accumulation: warp wr takes segments si == wr (mod 8)
        // bufc is in sorted order -> sequential reads, LDS + 2 FFMA per pixel
        {
            const unsigned short* sgr = segsm + ch * SEGW;
            const int nseg = sgr[0];
            const float* bp = bufc + lane * 129;
            #pragma unroll 1
            for (int si = 1 + wr; si <= nseg; si += 8) {
                int e     = sgr[si];               // uniform LDS
                int cls   = e >> 8;
                int start = e & 255;
                int end   = sgr[si + 1] & 255;     // next start / sentinel 128
                float s = 0.f, qq = 0.f;
                #pragma unroll 2
                for (int j = start; j < end; j++) {
                    float f = bp[j];               // sequential, conflict-free
                    s  += f;
                    qq += f * f;
                }
                accS[cls * 32 + lane] += s;        // race-free: class-disjoint mod 8
                accQ[cls * 32 + lane] += qq;
            }
        }
        pv = pvn;
    }
    __syncthreads();

    // single coalesced atomic flush
    #pragma unroll
    for (int i = t; i < CP1 * 32; i += 256) {
        int c = i >> 5, al = i & 31;
        atomicAdd(&gSums[c * AA + aBase + al], accS[i]);
        atomicAdd(&gSq[c * AA + aBase + al],   accQ[i]);
    }
}

// ---------------------------------------------------------------------------
// K2: grid = 361 blocks, one per (l,c) pair (ncov row 19 never read:
// lab0<=18). Each block recomputes ncov[l,:] pointwise (cheap) and reduces
// ratio * sum_a ncov[l,a]*(W[c,a]-W[l,a])^2 across 256 threads.
// ---------------------------------------------------------------------------
__global__ __launch_bounds__(256)
void cov_s_kernel(const float* __restrict__ fc,
                  const float* __restrict__ Ave,
                  const float* __restrict__ CoV,
                  const float* __restrict__ Amount,
                  const int* __restrict__ ratio_p) {
    __shared__ float red[8];
    const int l = blockIdx.x / CC;     // 0..18
    const int c = blockIdx.x % CC;     // 0..18
    const int t = threadIdx.x;         // 0..255 == feature index a
    const int lane = t & 31, wid = t >> 5;

    float cntv = gCount[l];
    float sums = gSums[l * AA + t];
    float sq   = gSq[l * AA + t];
    float avev = Ave[l * AA + t];
    float covv = CoV[l * AA + t];
    float amov = Amount[l];
    float wc   = fc[c * AA + t];
    float wl   = fc[l * AA + t];
    float r    = (float)(*ratio_p);    // low 4 LE bytes: correct for i32 & i64

    float cntc = (cntv == 0.f) ? 1.f : cntv;
    float ave  = sums / cntc;
    float var  = sq / cntc - ave * ave;
    float denom = cntv + amov;
    float wcv  = (denom > 0.f) ? (cntv / denom) : 0.f;
    float dd   = avev - ave;
    float ncov = covv * (1.f - wcv) + var * wcv + wcv * (1.f - wcv) * dd * dd;

    float d = wc - wl;
    float v = ncov * d * d;
    #pragma unroll
    for (int o = 16; o; o >>= 1) v += __shfl_down_sync(0xffffffffu, v, o);
    if (lane == 0) red[wid] = v;
    __syncthreads();
    if (t == 0) {
        float s = 0.f;
        #pragma unroll
        for (int k = 0; k < 8; k++) s += red[k];
        gS[l * CC + c] = r * s;
    }
}

// ---------------------------------------------------------------------------
// K3: out[n,c,h,w] = y[n,c,h,w] + 0.5 * S[l(n,h,w), c] * (l != 255)
// 8 blocks per (n,c) -> 1216 blocks (R16 showed grid 608 = only 4.1 CTA/SM,
// latency-bound at issue 20%); 256 threads, float4/uchar4.
// ---------------------------------------------------------------------------
__global__ __launch_bounds__(256, 8)
void aug_kernel(const float* __restrict__ y, float* __restrict__ out) {
    __shared__ float Ssm[CP1];
    const int t = threadIdx.x;                 // 0..255
    const int bq = blockIdx.x & 7;             // h-eighth
    const int nc = blockIdx.x >> 3;
    const int n = nc / CC;
    const int c = nc % CC;

    if (t < CP1) Ssm[t] = (t < CC) ? (0.5f * gS[t * CC + c]) : 0.f;
    __syncthreads();

    const size_t plane = ((size_t)n * CC + c) * (HH * WW);
    const int qoff = bq * (HH * WW / 32);      // in float4 units (512 per eighth)
    const float4* y4 = (const float4*)(y + plane) + qoff;
    float4*       o4 = (float4*)(out + plane) + qoff;
    const uchar4* l4 = (const uchar4*)(gLab + (size_t)n * (HH * WW)) + qoff;

    #pragma unroll
    for (int i = t; i < (HH * WW) / 32; i += 256) {
        uchar4 lb = l4[i];
        float4 v  = y4[i];
        if (lb.x != 255) v.x += Ssm[lb.x];
        if (lb.y != 255) v.y += Ssm[lb.y];
        if (lb.z != 255) v.z += Ssm[lb.z];
        if (lb.w != 255) v.w += Ssm[lb.w];
        o4[i] = v;
    }
}

// ---------------------------------------------------------------------------
extern "C" void kernel_launch(void* const* d_in, const int* in_sizes, int n_in,
                              void* d_out, int out_size) {
    const float* features = (const float*)d_in[0];
    const float* y        = (const float*)d_in[1];
    const float* fc       = (const float*)d_in[2];
    const float* Ave      = (const float*)d_in[3];
    const float* CoV      = (const float*)d_in[4];
    const float* Amount   = (const float*)d_in[5];
    const int*   target_w = (const int*)d_in[6];   // int32 or int64 (probed)
    const int*   ratio    = (const int*)d_in[7];
    float*       out      = (float*)d_out;

    // launch idx 0: dtype probe
    detect_kernel<<<1, 256>>>(target_w);
    // launch idx 1: zero accumulators
    zero_kernel<<<(CP1 * AA + 255) / 256, 256>>>();
    // launch idx 2: per-row label sort + position/segment extraction
    sort_kernel<<<NN * HH, 128>>>(target_w);

    // launch idx 3 (the ncu-captured slot): stats
    const int smem1 = (2 * ACOLS * 129 + 2 * CP1 * 32) * 4 + RPB * SEGW * 2;
    cudaFuncSetAttribute(stats_kernel, cudaFuncAttributeMaxDynamicSharedMemorySize, smem1);
    dim3 g1(8, HH / RPB, NN);
    stats_kernel<<<g1, 256, smem1>>>(features);

    // launch idx 4: covariance update + S table (one block per (l,c))
    cov_s_kernel<<<CC * CC, 256>>>(fc, Ave, CoV, Amount, ratio);

    // launch idx 5: output
    aug_kernel<<<NN * CC * 8, 256>>>(y, out);
}